// round 13
// baseline (speedup 1.0000x reference)
#include <cuda_runtime.h>
#include <cuda_bf16.h>
#include <cstdint>
#include <cstddef>

#define NN 100000
#define RR 6
#define EE 400000
#define FF 128
#define KT 768          // RR*FF (N dim of Z)
#define RN 600000       // RR*NN
#define RE 2400000      // RR*EE
#define MPAD 100096     // 782*128 padded rows for Xh/Z
#define NB2 98          // ceil(NN/1024)
#define GEMM_SMEM 104448  // 3 * 128*136*2 bytes

// ---------------- scratch (device globals; zero-initialized at load) --------
__device__ int   g_deg_out[RN];
__device__ int   g_deg_in[RN];
__device__ float g_norm_src[RN];
__device__ float g_norm_dst[RN];
__device__ int   g_deg2[NN];
__device__ int   g_offs2[NN + 1];
__device__ int   g_bsums[NB2];
__device__ int   g_boffs[NB2];
__device__ int   g_cursor2[NN];
__device__ int2  g_epw[RE];        // {src | (r<<17), bitcast(weight)}
__device__ float g_c[RN];          // layer-2 coefficients
__device__ float g_bsum1[FF];
__device__ __nv_bfloat16 g_Xh[(size_t)MPAD * FF];   // x in bf16 (pad rows stay 0)
__device__ __nv_bfloat16 g_Bh[FF * KT];             // W1 repacked [k][r*128+j] hi
__device__ __nv_bfloat16 g_Bl[FF * KT];             // lo residual
__device__ __nv_bfloat16 g_Z[(size_t)MPAD * KT];    // Z = X @ W1cat, bf16
__device__ float g_h[(size_t)NN * FF];              // layer-1 output (post-relu)
__device__ float g_s[RR * FF];                      // layer-2 pooled vectors

__global__ void k_gemmZ();

// ---- side stream + events + smem opt-in, created at load time --------------
static cudaStream_t g_s2;
static cudaEvent_t  g_evF, g_evJ;
namespace {
struct StreamInit {
    StreamInit() {
        cudaStreamCreateWithFlags(&g_s2, cudaStreamNonBlocking);
        cudaEventCreateWithFlags(&g_evF, cudaEventDisableTiming);
        cudaEventCreateWithFlags(&g_evJ, cudaEventDisableTiming);
        cudaFuncSetAttribute(k_gemmZ, cudaFuncAttributeMaxDynamicSharedMemorySize,
                             GEMM_SMEM);
    }
};
StreamInit s_streamInit;
}

// ---------------- helpers ----------------------------------------------------
__device__ __forceinline__ uint32_t smem_u32(const void* p) {
    return (uint32_t)__cvta_generic_to_shared(p);
}
__device__ __forceinline__ void cp_async16(void* s, const void* g) {
    uint32_t sa = smem_u32(s);
    asm volatile("cp.async.cg.shared.global [%0], [%1], 16;" :: "r"(sa), "l"(g));
}
__device__ __forceinline__ void ldmx4(uint32_t* r, uint32_t addr) {
    asm volatile("ldmatrix.sync.aligned.m8n8.x4.shared.b16 {%0,%1,%2,%3}, [%4];"
        : "=r"(r[0]), "=r"(r[1]), "=r"(r[2]), "=r"(r[3]) : "r"(addr));
}
__device__ __forceinline__ void ldmx4t(uint32_t* r, uint32_t addr) {
    asm volatile("ldmatrix.sync.aligned.m8n8.x4.trans.shared.b16 {%0,%1,%2,%3}, [%4];"
        : "=r"(r[0]), "=r"(r[1]), "=r"(r[2]), "=r"(r[3]) : "r"(addr));
}
__device__ __forceinline__ void mma16816(float* d, const uint32_t* a, const uint32_t* b) {
    asm volatile(
        "mma.sync.aligned.m16n8k16.row.col.f32.bf16.bf16.f32 "
        "{%0,%1,%2,%3}, {%4,%5,%6,%7}, {%8,%9}, {%0,%1,%2,%3};"
        : "+f"(d[0]), "+f"(d[1]), "+f"(d[2]), "+f"(d[3])
        : "r"(a[0]), "r"(a[1]), "r"(a[2]), "r"(a[3]), "r"(b[0]), "r"(b[1]));
}
__device__ __forceinline__ void bfsplit(float v, __nv_bfloat16& h, __nv_bfloat16& l) {
    h = __float2bfloat16_rn(v);
    l = __float2bfloat16_rn(v - __bfloat162float(h));
}
__device__ __forceinline__ uint32_t packbf2(float a, float b) {
    __nv_bfloat16 ha = __float2bfloat16_rn(a), hb = __float2bfloat16_rn(b);
    return (uint32_t)__bfloat16_as_ushort(ha) | ((uint32_t)__bfloat16_as_ushort(hb) << 16);
}

// ---------------- graph prep -------------------------------------------------
__global__ void k_deg(const int* __restrict__ src, const int* __restrict__ dst) {
    int i = blockIdx.x * blockDim.x + threadIdx.x;
    if (i >= RE) return;
    int r = i / EE;
    atomicAdd(&g_deg_out[r * NN + src[i]], 1);
    atomicAdd(&g_deg_in [r * NN + dst[i]], 1);
}

__global__ void k_norm() {
    int i = blockIdx.x * blockDim.x + threadIdx.x;
    if (i >= RN) return;
    int d0 = g_deg_out[i], d1 = g_deg_in[i];
    g_norm_src[i] = d0 > 0 ? rsqrtf((float)d0) : 0.f;
    g_norm_dst[i] = d1 > 0 ? rsqrtf((float)d1) : 0.f;
}

__global__ void k_deg2() {
    int n = blockIdx.x * blockDim.x + threadIdx.x;
    if (n >= NN) return;
    int a = 0;
#pragma unroll
    for (int r = 0; r < RR; r++) a += g_deg_in[r * NN + n];
    g_deg2[n] = a;
}

__global__ void k_dscan1() {
    __shared__ int s[1024];
    int t = threadIdx.x, i = blockIdx.x * 1024 + t;
    int v = (i < NN) ? g_deg2[i] : 0;
    s[t] = v; __syncthreads();
    for (int d = 1; d < 1024; d <<= 1) {
        int u = (t >= d) ? s[t - d] : 0;
        __syncthreads();
        s[t] += u; __syncthreads();
    }
    if (i < NN) g_offs2[i] = s[t] - v;
    if (t == 1023) g_bsums[blockIdx.x] = s[1023];
}

__global__ void k_dscan2() {
    __shared__ int s[128];
    int t = threadIdx.x;
    int v = (t < NB2) ? g_bsums[t] : 0;
    s[t] = v; __syncthreads();
    for (int d = 1; d < 128; d <<= 1) {
        int u = (t >= d) ? s[t - d] : 0;
        __syncthreads();
        s[t] += u; __syncthreads();
    }
    if (t < NB2) g_boffs[t] = s[t] - v;
}

__global__ void k_dscan3() {
    int t = threadIdx.x, i = blockIdx.x * 1024 + t;
    if (i < NN) g_offs2[i] += g_boffs[blockIdx.x];
    if (i == 0) g_offs2[NN] = RE;
}

// merged CSR keyed by dst; packed (idx, weight) payload; layer-2 coefficients
__global__ void k_fill2(const int* __restrict__ src, const int* __restrict__ dst) {
    int i = blockIdx.x * blockDim.x + threadIdx.x;
    if (i >= RE) return;
    int r = i / EE, s = src[i], d = dst[i];
    float nd = g_norm_dst[r * NN + d];
    int pos  = atomicAdd(&g_cursor2[d], 1);
    int slot = g_offs2[d] + pos;
    float w  = g_norm_src[r * NN + s] * nd;
    g_epw[slot] = make_int2(s | (r << 17), __float_as_int(w));
    atomicAdd(&g_c[r * NN + s], nd);
}

// ---------------- operand prep ----------------------------------------------
__global__ void k_prepX(const float* __restrict__ x) {
    int i = blockIdx.x * blockDim.x + threadIdx.x;   // NN*FF/4 = 3.2M
    if (i >= NN * FF / 4) return;
    float4 v = ((const float4*)x)[i];
    uint2 o;
    o.x = packbf2(v.x, v.y);
    o.y = packbf2(v.z, v.w);
    ((uint2*)g_Xh)[i] = o;
}

__global__ void k_prepB(const float* __restrict__ W1) {
    int i = blockIdx.x * blockDim.x + threadIdx.x;   // 6*128*128 = 98304
    if (i >= RR * FF * FF) return;
    int r = i / (FF * FF), rem = i % (FF * FF);
    int k = rem / FF, j = rem % FF;
    __nv_bfloat16 h, l;
    bfsplit(W1[i], h, l);
    int o = k * KT + r * FF + j;
    g_Bh[o] = h; g_Bl[o] = l;
}

__global__ void k_bsum1(const float* __restrict__ b1) {
    int t = threadIdx.x;
    float a = 0.f;
#pragma unroll
    for (int r = 0; r < RR; r++) a += b1[r * FF + t];
    g_bsum1[t] = a;
}

// ---------------- GEMM: Z[100k,768] = Xh[100k,128] @ B[128,768], 2-term -----
// Whole-K resident: A(128x128) + Bh + Bl in 104KB dynamic smem, one cp.async
// burst + one barrier, then 256 MMAs/warp uninterrupted. Warps 2M x 4N (64x32).
__global__ void __launch_bounds__(256, 2) k_gemmZ() {
    extern __shared__ char dynsmem[];
    __nv_bfloat16* Ash = (__nv_bfloat16*)dynsmem;             // [128][136]
    __nv_bfloat16* Bsh = (__nv_bfloat16*)(dynsmem + 34816);   // [128][136]
    __nv_bfloat16* Bsl = (__nv_bfloat16*)(dynsmem + 69632);   // [128][136]
    const int LDS = 136;

    int tid = threadIdx.x, lane = tid & 31, warp = tid >> 5;
    int wm = warp & 1, wn = warp >> 1;                         // 2M x 4N
    size_t m0 = (size_t)blockIdx.x * 128;
    int n0 = blockIdx.y * 128;

    // ---- single cp.async burst: 2048 16B chunks per tile ----
    for (int c = tid; c < 2048; c += 256) {
        int row = c >> 4, col8 = (c & 15) * 8;
        cp_async16(&Ash[row * LDS + col8], &g_Xh[(m0 + row) * FF + col8]);
        cp_async16(&Bsh[row * LDS + col8], &g_Bh[row * KT + n0 + col8]);
        cp_async16(&Bsl[row * LDS + col8], &g_Bl[row * KT + n0 + col8]);
    }
    asm volatile("cp.async.commit_group;");
    asm volatile("cp.async.wait_group 0;");
    __syncthreads();

    float acc[4][4][4];
#pragma unroll
    for (int i = 0; i < 4; i++)
#pragma unroll
        for (int j = 0; j < 4; j++)
#pragma unroll
            for (int q = 0; q < 4; q++) acc[i][j][q] = 0.f;

    int aRow = wm * 64 + (lane & 15);
    int aSel = (lane >> 4) * 8;                  // k-offset within 16
    int bKr  = (lane & 7) + ((lane >> 3) & 1) * 8;
    int bSel = ((lane >> 4) & 1) * 8;            // n-offset within 16
    int bCol = wn * 32;

#pragma unroll
    for (int kc = 0; kc < 8; kc++) {
        uint32_t a[4][4], bh[4][2], bl[4][2];
#pragma unroll
        for (int i = 0; i < 4; i++)
            ldmx4(a[i], smem_u32(&Ash[(aRow + i * 16) * LDS + kc * 16 + aSel]));
#pragma unroll
        for (int p = 0; p < 2; p++) {
            uint32_t r4[4];
            ldmx4t(r4, smem_u32(&Bsh[(kc * 16 + bKr) * LDS + bCol + p * 16 + bSel]));
            bh[2 * p][0] = r4[0]; bh[2 * p][1] = r4[1];
            bh[2 * p + 1][0] = r4[2]; bh[2 * p + 1][1] = r4[3];
            ldmx4t(r4, smem_u32(&Bsl[(kc * 16 + bKr) * LDS + bCol + p * 16 + bSel]));
            bl[2 * p][0] = r4[0]; bl[2 * p][1] = r4[1];
            bl[2 * p + 1][0] = r4[2]; bl[2 * p + 1][1] = r4[3];
        }
#pragma unroll
        for (int i = 0; i < 4; i++)
#pragma unroll
            for (int j = 0; j < 4; j++) {
                mma16816(acc[i][j], a[i], bh[j]);
                mma16816(acc[i][j], a[i], bl[j]);
            }
    }

    // ---- epilogue: store Z as bf16 (rows padded, no guard) ----
    size_t rBase = m0 + wm * 64 + (lane >> 2);
    int cBase = n0 + wn * 32 + (lane & 3) * 2;
#pragma unroll
    for (int i = 0; i < 4; i++) {
        size_t ra = rBase + i * 16, rb = ra + 8;
#pragma unroll
        for (int j = 0; j < 4; j++) {
            int col = cBase + j * 8;
            *(uint32_t*)&g_Z[ra * KT + col] = packbf2(acc[i][j][0], acc[i][j][1]);
            *(uint32_t*)&g_Z[rb * KT + col] = packbf2(acc[i][j][2], acc[i][j][3]);
        }
    }
}

// ---------------- aggregation: h = relu(sum_e w_e * Z[src_e, r_e] + bsum1) ---
__global__ void k_agg2() {
    int w = (blockIdx.x * blockDim.x + threadIdx.x) >> 5;   // dst node
    int lane = threadIdx.x & 31;
    if (w >= NN) return;
    int beg = g_offs2[w], end = g_offs2[w + 1];
    float a0 = 0.f, a1 = 0.f, a2 = 0.f, a3 = 0.f;
    int j = beg;
    for (; j + 3 < end; j += 4) {
        int2 e0 = g_epw[j], e1 = g_epw[j + 1], e2 = g_epw[j + 2], e3 = g_epw[j + 3];
        size_t o0 = (size_t)(e0.x & 131071) * KT + (e0.x >> 17) * FF + lane * 4;
        size_t o1 = (size_t)(e1.x & 131071) * KT + (e1.x >> 17) * FF + lane * 4;
        size_t o2 = (size_t)(e2.x & 131071) * KT + (e2.x >> 17) * FF + lane * 4;
        size_t o3 = (size_t)(e3.x & 131071) * KT + (e3.x >> 17) * FF + lane * 4;
        uint2 z0 = *(const uint2*)&g_Z[o0];
        uint2 z1 = *(const uint2*)&g_Z[o1];
        uint2 z2 = *(const uint2*)&g_Z[o2];
        uint2 z3 = *(const uint2*)&g_Z[o3];
        float w0 = __int_as_float(e0.y), w1 = __int_as_float(e1.y);
        float w2 = __int_as_float(e2.y), w3 = __int_as_float(e3.y);
        float2 u;
        u = __bfloat1622float2(*(__nv_bfloat162*)&z0.x); a0 += w0 * u.x; a1 += w0 * u.y;
        u = __bfloat1622float2(*(__nv_bfloat162*)&z0.y); a2 += w0 * u.x; a3 += w0 * u.y;
        u = __bfloat1622float2(*(__nv_bfloat162*)&z1.x); a0 += w1 * u.x; a1 += w1 * u.y;
        u = __bfloat1622float2(*(__nv_bfloat162*)&z1.y); a2 += w1 * u.x; a3 += w1 * u.y;
        u = __bfloat1622float2(*(__nv_bfloat162*)&z2.x); a0 += w2 * u.x; a1 += w2 * u.y;
        u = __bfloat1622float2(*(__nv_bfloat162*)&z2.y); a2 += w2 * u.x; a3 += w2 * u.y;
        u = __bfloat1622float2(*(__nv_bfloat162*)&z3.x); a0 += w3 * u.x; a1 += w3 * u.y;
        u = __bfloat1622float2(*(__nv_bfloat162*)&z3.y); a2 += w3 * u.x; a3 += w3 * u.y;
    }
    for (; j < end; j++) {
        int2 e = g_epw[j];
        float wt = __int_as_float(e.y);
        size_t o = (size_t)(e.x & 131071) * KT + (e.x >> 17) * FF + lane * 4;
        uint2 z = *(const uint2*)&g_Z[o];
        float2 u;
        u = __bfloat1622float2(*(__nv_bfloat162*)&z.x); a0 += wt * u.x; a1 += wt * u.y;
        u = __bfloat1622float2(*(__nv_bfloat162*)&z.y); a2 += wt * u.x; a3 += wt * u.y;
    }
    float4 bb = *(const float4*)&g_bsum1[lane * 4];
    float4 o;
    o.x = fmaxf(a0 + bb.x, 0.f);
    o.y = fmaxf(a1 + bb.y, 0.f);
    o.z = fmaxf(a2 + bb.z, 0.f);
    o.w = fmaxf(a3 + bb.w, 0.f);
    *(float4*)&g_h[(size_t)w * FF + lane * 4] = o;
}

// ---------------- layer-2 collapse + classifier ------------------------------
__global__ void k_reduce() {
    __shared__ float wc[RR][128];
    int t = threadIdx.x;
    int base = blockIdx.x * 128;
    int n = base + t;
#pragma unroll
    for (int r = 0; r < RR; r++)
        wc[r][t] = (n < NN) ? g_norm_src[r * NN + n] * g_c[r * NN + n] : 0.f;
    __syncthreads();
    float acc[RR] = {0.f, 0.f, 0.f, 0.f, 0.f, 0.f};
    int lim = min(128, NN - base);
    for (int ni = 0; ni < lim; ni++) {
        float hv = g_h[(size_t)(base + ni) * FF + t];
#pragma unroll
        for (int r = 0; r < RR; r++) acc[r] += wc[r][ni] * hv;
    }
#pragma unroll
    for (int r = 0; r < RR; r++) atomicAdd(&g_s[r * FF + t], acc[r]);
}

__global__ void k_final(const float* __restrict__ W2, const float* __restrict__ b2,
                        const float* __restrict__ Wc, const float* __restrict__ bc,
                        float* __restrict__ out) {
    __shared__ float g[FF];
    int f = threadIdx.x;
    float acc = 0.f;
    for (int rk = 0; rk < RR * FF; rk++)
        acc += g_s[rk] * W2[(size_t)rk * FF + f];
    float gb = 0.f;
#pragma unroll
    for (int r = 0; r < RR; r++) gb += b2[r * FF + f];
    g[f] = acc * (1.f / NN) + gb;
    __syncthreads();
    if (f < 2) {
        float o = bc[f];
        for (int k = 0; k < FF; k++) o += g[k] * Wc[k * 2 + f];
        out[f] = o;
    }
}

// ---------------- launch ----------------
extern "C" void kernel_launch(void* const* d_in, const int* in_sizes, int n_in,
                              void* d_out, int out_size) {
    const float* x    = (const float*)d_in[0];
    const int*   esrc = (const int*)  d_in[1];
    const int*   edst = (const int*)  d_in[2];
    const float* W1   = (const float*)d_in[3];
    const float* b1   = (const float*)d_in[4];
    const float* W2   = (const float*)d_in[5];
    const float* b2   = (const float*)d_in[6];
    const float* Wc   = (const float*)d_in[7];
    const float* bc   = (const float*)d_in[8];
    float* out = (float*)d_out;

    void *p_do, *p_di, *p_cur, *p_c, *p_s;
    cudaGetSymbolAddress(&p_do,  g_deg_out);
    cudaGetSymbolAddress(&p_di,  g_deg_in);
    cudaGetSymbolAddress(&p_cur, g_cursor2);
    cudaGetSymbolAddress(&p_c,   g_c);
    cudaGetSymbolAddress(&p_s,   g_s);

    // ---- fork: side stream runs the dense (tensor-pipe) chain ----
    cudaEventRecord(g_evF, 0);
    cudaStreamWaitEvent(g_s2, g_evF, 0);

    k_prepX<<<(NN * FF / 4 + 255) / 256, 256, 0, g_s2>>>(x);
    k_prepB<<<(RR * FF * FF + 255) / 256, 256, 0, g_s2>>>(W1);
    k_bsum1<<<1, FF, 0, g_s2>>>(b1);
    k_gemmZ<<<dim3(782, 6), 256, GEMM_SMEM, g_s2>>>();
    cudaEventRecord(g_evJ, g_s2);

    // ---- main stream: graph prep (L2-atomic-bound) ----
    cudaMemsetAsync(p_do,  0, (size_t)RN * 4, 0);
    cudaMemsetAsync(p_di,  0, (size_t)RN * 4, 0);
    cudaMemsetAsync(p_cur, 0, (size_t)NN * 4, 0);
    cudaMemsetAsync(p_c,   0, (size_t)RN * 4, 0);
    cudaMemsetAsync(p_s,   0, (size_t)RR * FF * 4, 0);

    k_deg  <<<(RE + 255) / 256, 256>>>(esrc, edst);
    k_norm <<<(RN + 255) / 256, 256>>>();
    k_deg2 <<<(NN + 255) / 256, 256>>>();
    k_dscan1<<<NB2, 1024>>>();
    k_dscan2<<<1, 128>>>();
    k_dscan3<<<NB2, 1024>>>();
    k_fill2<<<(RE + 255) / 256, 256>>>(esrc, edst);

    // ---- join: aggregation needs both Z (s2) and the CSR (main) ----
    cudaStreamWaitEvent(0, g_evJ, 0);
    k_agg2 <<<(NN * 32 + 255) / 256, 256>>>();
    k_reduce<<<(NN + 127) / 128, 128>>>();
    k_final<<<1, FF>>>(W2, b2, Wc, bc, out);
}

// round 15
// speedup vs baseline: 1.2860x; 1.2860x over previous
#include <cuda_runtime.h>
#include <cuda_bf16.h>
#include <cuda_fp16.h>
#include <cstdint>
#include <cstddef>

#define NN 100000
#define RR 6
#define EE 400000
#define FF 128
#define KT 768          // RR*FF (N dim of Z)
#define RN 600000       // RR*NN
#define RE 2400000      // RR*EE
#define MPAD 100096     // 782*128 padded rows for Xh/Z
#define NB2 98          // ceil(NN/1024)
#define GEMM_SMEM 69632 // 2 * 128*136*2 bytes

// ---------------- scratch (device globals; zero-initialized at load) --------
__device__ int   g_deg_out[RN];
__device__ int   g_deg_in[RN];
__device__ float g_norm_src[RN];
__device__ float g_norm_dst[RN];
__device__ int   g_deg2[NN];
__device__ int   g_offs2[NN + 1];
__device__ int   g_bsums[NB2];
__device__ int   g_boffs[NB2];
__device__ int   g_cursor2[NN];
__device__ int2  g_epw[RE];        // {src | (r<<17), bitcast(weight)}
__device__ float g_c[RN];          // layer-2 coefficients
__device__ float g_bsum1[FF];
__device__ __half g_Xh[(size_t)MPAD * FF];          // x in fp16 (pad rows stay 0)
__device__ __half g_Bf[FF * KT];                    // W1 repacked [k][r*128+j] fp16
__device__ __nv_bfloat16 g_Z[(size_t)MPAD * KT];    // Z = X @ W1cat, bf16
__device__ float g_h[(size_t)NN * FF];              // layer-1 output (post-relu)
__device__ float g_s[RR * FF];                      // layer-2 pooled vectors
__device__ float g_g[FF];                           // pooled graph embedding accum

__global__ void k_gemmZ();

// ---- side stream + events + smem opt-in, created at load time --------------
static cudaStream_t g_s2;
static cudaEvent_t  g_evF, g_evJ;
namespace {
struct StreamInit {
    StreamInit() {
        cudaStreamCreateWithFlags(&g_s2, cudaStreamNonBlocking);
        cudaEventCreateWithFlags(&g_evF, cudaEventDisableTiming);
        cudaEventCreateWithFlags(&g_evJ, cudaEventDisableTiming);
        cudaFuncSetAttribute(k_gemmZ, cudaFuncAttributeMaxDynamicSharedMemorySize,
                             GEMM_SMEM);
    }
};
StreamInit s_streamInit;
}

// ---------------- helpers ----------------------------------------------------
__device__ __forceinline__ uint32_t smem_u32(const void* p) {
    return (uint32_t)__cvta_generic_to_shared(p);
}
__device__ __forceinline__ void cp_async16(void* s, const void* g) {
    uint32_t sa = smem_u32(s);
    asm volatile("cp.async.cg.shared.global [%0], [%1], 16;" :: "r"(sa), "l"(g));
}
__device__ __forceinline__ void ldmx4(uint32_t* r, uint32_t addr) {
    asm volatile("ldmatrix.sync.aligned.m8n8.x4.shared.b16 {%0,%1,%2,%3}, [%4];"
        : "=r"(r[0]), "=r"(r[1]), "=r"(r[2]), "=r"(r[3]) : "r"(addr));
}
__device__ __forceinline__ void ldmx4t(uint32_t* r, uint32_t addr) {
    asm volatile("ldmatrix.sync.aligned.m8n8.x4.trans.shared.b16 {%0,%1,%2,%3}, [%4];"
        : "=r"(r[0]), "=r"(r[1]), "=r"(r[2]), "=r"(r[3]) : "r"(addr));
}
__device__ __forceinline__ void mma16816(float* d, const uint32_t* a, const uint32_t* b) {
    asm volatile(
        "mma.sync.aligned.m16n8k16.row.col.f32.f16.f16.f32 "
        "{%0,%1,%2,%3}, {%4,%5,%6,%7}, {%8,%9}, {%0,%1,%2,%3};"
        : "+f"(d[0]), "+f"(d[1]), "+f"(d[2]), "+f"(d[3])
        : "r"(a[0]), "r"(a[1]), "r"(a[2]), "r"(a[3]), "r"(b[0]), "r"(b[1]));
}
__device__ __forceinline__ uint32_t packbf2(float a, float b) {
    __nv_bfloat16 ha = __float2bfloat16_rn(a), hb = __float2bfloat16_rn(b);
    return (uint32_t)__bfloat16_as_ushort(ha) | ((uint32_t)__bfloat16_as_ushort(hb) << 16);
}

// ---------------- graph prep -------------------------------------------------
__global__ void k_deg(const int* __restrict__ src, const int* __restrict__ dst) {
    int i = blockIdx.x * blockDim.x + threadIdx.x;
    if (i >= RE) return;
    int r = i / EE;
    atomicAdd(&g_deg_out[r * NN + src[i]], 1);
    atomicAdd(&g_deg_in [r * NN + dst[i]], 1);
}

__global__ void k_norm() {
    int i = blockIdx.x * blockDim.x + threadIdx.x;
    if (i >= RN) return;
    int d0 = g_deg_out[i], d1 = g_deg_in[i];
    g_norm_src[i] = d0 > 0 ? rsqrtf((float)d0) : 0.f;
    g_norm_dst[i] = d1 > 0 ? rsqrtf((float)d1) : 0.f;
}

__global__ void k_deg2() {
    int n = blockIdx.x * blockDim.x + threadIdx.x;
    if (n >= NN) return;
    int a = 0;
#pragma unroll
    for (int r = 0; r < RR; r++) a += g_deg_in[r * NN + n];
    g_deg2[n] = a;
}

__global__ void k_dscan1() {
    __shared__ int s[1024];
    int t = threadIdx.x, i = blockIdx.x * 1024 + t;
    int v = (i < NN) ? g_deg2[i] : 0;
    s[t] = v; __syncthreads();
    for (int d = 1; d < 1024; d <<= 1) {
        int u = (t >= d) ? s[t - d] : 0;
        __syncthreads();
        s[t] += u; __syncthreads();
    }
    if (i < NN) g_offs2[i] = s[t] - v;
    if (t == 1023) g_bsums[blockIdx.x] = s[1023];
}

__global__ void k_dscan2() {
    __shared__ int s[128];
    int t = threadIdx.x;
    int v = (t < NB2) ? g_bsums[t] : 0;
    s[t] = v; __syncthreads();
    for (int d = 1; d < 128; d <<= 1) {
        int u = (t >= d) ? s[t - d] : 0;
        __syncthreads();
        s[t] += u; __syncthreads();
    }
    if (t < NB2) g_boffs[t] = s[t] - v;
}

__global__ void k_dscan3() {
    int t = threadIdx.x, i = blockIdx.x * 1024 + t;
    if (i < NN) g_offs2[i] += g_boffs[blockIdx.x];
    if (i == 0) g_offs2[NN] = RE;
}

// merged CSR keyed by dst; packed (idx, weight) payload; layer-2 coefficients
__global__ void k_fill2(const int* __restrict__ src, const int* __restrict__ dst) {
    int i = blockIdx.x * blockDim.x + threadIdx.x;
    if (i >= RE) return;
    int r = i / EE, s = src[i], d = dst[i];
    float nd = g_norm_dst[r * NN + d];
    int pos  = atomicAdd(&g_cursor2[d], 1);
    int slot = g_offs2[d] + pos;
    float w  = g_norm_src[r * NN + s] * nd;
    g_epw[slot] = make_int2(s | (r << 17), __float_as_int(w));
    atomicAdd(&g_c[r * NN + s], nd);
}

// ---------------- operand prep ----------------------------------------------
__global__ void k_prepX(const float* __restrict__ x) {
    int i = blockIdx.x * blockDim.x + threadIdx.x;   // NN*FF/4 = 3.2M
    if (i >= NN * FF / 4) return;
    float4 v = ((const float4*)x)[i];
    __half2 h0 = __floats2half2_rn(v.x, v.y);
    __half2 h1 = __floats2half2_rn(v.z, v.w);
    uint2 o;
    o.x = *(uint32_t*)&h0;
    o.y = *(uint32_t*)&h1;
    ((uint2*)g_Xh)[i] = o;
}

__global__ void k_prepB(const float* __restrict__ W1) {
    int i = blockIdx.x * blockDim.x + threadIdx.x;   // 6*128*128 = 98304
    if (i >= RR * FF * FF) return;
    int r = i / (FF * FF), rem = i % (FF * FF);
    int k = rem / FF, j = rem % FF;
    g_Bf[k * KT + r * FF + j] = __float2half_rn(W1[i]);
}

__global__ void k_bsum1(const float* __restrict__ b1) {
    int t = threadIdx.x;
    float a = 0.f;
#pragma unroll
    for (int r = 0; r < RR; r++) a += b1[r * FF + t];
    g_bsum1[t] = a;
}

// ---------------- GEMM: Z[100k,768] = Xh[100k,128] @ Bf[128,768], fp16 ------
// Whole-K resident: A(128x128) + B in 68KB dynamic smem, one cp.async burst +
// one barrier, then 128 MMAs/warp uninterrupted. Warps 2M x 4N (64x32 tiles).
__global__ void __launch_bounds__(256, 2) k_gemmZ() {
    extern __shared__ char dynsmem[];
    __half* Ash = (__half*)dynsmem;             // [128][136]
    __half* Bsh = (__half*)(dynsmem + 34816);   // [128][136]
    const int LDS = 136;

    int tid = threadIdx.x, lane = tid & 31, warp = tid >> 5;
    int wm = warp & 1, wn = warp >> 1;                         // 2M x 4N
    size_t m0 = (size_t)blockIdx.x * 128;
    int n0 = blockIdx.y * 128;

    // ---- single cp.async burst: 2048 16B chunks per tile ----
    for (int c = tid; c < 2048; c += 256) {
        int row = c >> 4, col8 = (c & 15) * 8;
        cp_async16(&Ash[row * LDS + col8], &g_Xh[(m0 + row) * FF + col8]);
        cp_async16(&Bsh[row * LDS + col8], &g_Bf[row * KT + n0 + col8]);
    }
    asm volatile("cp.async.commit_group;");
    asm volatile("cp.async.wait_group 0;");
    __syncthreads();

    float acc[4][4][4];
#pragma unroll
    for (int i = 0; i < 4; i++)
#pragma unroll
        for (int j = 0; j < 4; j++)
#pragma unroll
            for (int q = 0; q < 4; q++) acc[i][j][q] = 0.f;

    int aRow = wm * 64 + (lane & 15);
    int aSel = (lane >> 4) * 8;                  // k-offset within 16
    int bKr  = (lane & 7) + ((lane >> 3) & 1) * 8;
    int bSel = ((lane >> 4) & 1) * 8;            // n-offset within 16
    int bCol = wn * 32;

#pragma unroll
    for (int kc = 0; kc < 8; kc++) {
        uint32_t a[4][4], bf[4][2];
#pragma unroll
        for (int i = 0; i < 4; i++)
            ldmx4(a[i], smem_u32(&Ash[(aRow + i * 16) * LDS + kc * 16 + aSel]));
#pragma unroll
        for (int p = 0; p < 2; p++) {
            uint32_t r4[4];
            ldmx4t(r4, smem_u32(&Bsh[(kc * 16 + bKr) * LDS + bCol + p * 16 + bSel]));
            bf[2 * p][0] = r4[0]; bf[2 * p][1] = r4[1];
            bf[2 * p + 1][0] = r4[2]; bf[2 * p + 1][1] = r4[3];
        }
#pragma unroll
        for (int i = 0; i < 4; i++)
#pragma unroll
            for (int j = 0; j < 4; j++)
                mma16816(acc[i][j], a[i], bf[j]);
    }

    // ---- epilogue: store Z as bf16 (rows padded, no guard) ----
    size_t rBase = m0 + wm * 64 + (lane >> 2);
    int cBase = n0 + wn * 32 + (lane & 3) * 2;
#pragma unroll
    for (int i = 0; i < 4; i++) {
        size_t ra = rBase + i * 16, rb = ra + 8;
#pragma unroll
        for (int j = 0; j < 4; j++) {
            int col = cBase + j * 8;
            *(uint32_t*)&g_Z[ra * KT + col] = packbf2(acc[i][j][0], acc[i][j][1]);
            *(uint32_t*)&g_Z[rb * KT + col] = packbf2(acc[i][j][2], acc[i][j][3]);
        }
    }
}

// ---------------- aggregation: h = relu(sum_e w_e * Z[src_e, r_e] + bsum1) ---
__global__ void k_agg2() {
    int w = (blockIdx.x * blockDim.x + threadIdx.x) >> 5;   // dst node
    int lane = threadIdx.x & 31;
    if (w >= NN) return;
    int beg = g_offs2[w], end = g_offs2[w + 1];
    float a0 = 0.f, a1 = 0.f, a2 = 0.f, a3 = 0.f;
    int j = beg;
    for (; j + 3 < end; j += 4) {
        int2 e0 = g_epw[j], e1 = g_epw[j + 1], e2 = g_epw[j + 2], e3 = g_epw[j + 3];
        size_t o0 = (size_t)(e0.x & 131071) * KT + (e0.x >> 17) * FF + lane * 4;
        size_t o1 = (size_t)(e1.x & 131071) * KT + (e1.x >> 17) * FF + lane * 4;
        size_t o2 = (size_t)(e2.x & 131071) * KT + (e2.x >> 17) * FF + lane * 4;
        size_t o3 = (size_t)(e3.x & 131071) * KT + (e3.x >> 17) * FF + lane * 4;
        uint2 z0 = *(const uint2*)&g_Z[o0];
        uint2 z1 = *(const uint2*)&g_Z[o1];
        uint2 z2 = *(const uint2*)&g_Z[o2];
        uint2 z3 = *(const uint2*)&g_Z[o3];
        float w0 = __int_as_float(e0.y), w1 = __int_as_float(e1.y);
        float w2 = __int_as_float(e2.y), w3 = __int_as_float(e3.y);
        float2 u;
        u = __bfloat1622float2(*(__nv_bfloat162*)&z0.x); a0 += w0 * u.x; a1 += w0 * u.y;
        u = __bfloat1622float2(*(__nv_bfloat162*)&z0.y); a2 += w0 * u.x; a3 += w0 * u.y;
        u = __bfloat1622float2(*(__nv_bfloat162*)&z1.x); a0 += w1 * u.x; a1 += w1 * u.y;
        u = __bfloat1622float2(*(__nv_bfloat162*)&z1.y); a2 += w1 * u.x; a3 += w1 * u.y;
        u = __bfloat1622float2(*(__nv_bfloat162*)&z2.x); a0 += w2 * u.x; a1 += w2 * u.y;
        u = __bfloat1622float2(*(__nv_bfloat162*)&z2.y); a2 += w2 * u.x; a3 += w2 * u.y;
        u = __bfloat1622float2(*(__nv_bfloat162*)&z3.x); a0 += w3 * u.x; a1 += w3 * u.y;
        u = __bfloat1622float2(*(__nv_bfloat162*)&z3.y); a2 += w3 * u.x; a3 += w3 * u.y;
    }
    for (; j < end; j++) {
        int2 e = g_epw[j];
        float wt = __int_as_float(e.y);
        size_t o = (size_t)(e.x & 131071) * KT + (e.x >> 17) * FF + lane * 4;
        uint2 z = *(const uint2*)&g_Z[o];
        float2 u;
        u = __bfloat1622float2(*(__nv_bfloat162*)&z.x); a0 += wt * u.x; a1 += wt * u.y;
        u = __bfloat1622float2(*(__nv_bfloat162*)&z.y); a2 += wt * u.x; a3 += wt * u.y;
    }
    float4 bb = *(const float4*)&g_bsum1[lane * 4];
    float4 o;
    o.x = fmaxf(a0 + bb.x, 0.f);
    o.y = fmaxf(a1 + bb.y, 0.f);
    o.z = fmaxf(a2 + bb.z, 0.f);
    o.w = fmaxf(a3 + bb.w, 0.f);
    *(float4*)&g_h[(size_t)w * FF + lane * 4] = o;
}

// ---------------- layer-2 collapse + classifier ------------------------------
__global__ void k_reduce() {
    __shared__ float wc[RR][128];
    int t = threadIdx.x;
    int base = blockIdx.x * 128;
    int n = base + t;
#pragma unroll
    for (int r = 0; r < RR; r++)
        wc[r][t] = (n < NN) ? g_norm_src[r * NN + n] * g_c[r * NN + n] : 0.f;
    __syncthreads();
    float acc[RR] = {0.f, 0.f, 0.f, 0.f, 0.f, 0.f};
    int lim = min(128, NN - base);
    for (int ni = 0; ni < lim; ni++) {
        float hv = g_h[(size_t)(base + ni) * FF + t];
#pragma unroll
        for (int r = 0; r < RR; r++) acc[r] += wc[r][ni] * hv;
    }
#pragma unroll
    for (int r = 0; r < RR; r++) atomicAdd(&g_s[r * FF + t], acc[r]);
}

// per-relation block: g += s_r @ W2_r (6 blocks in parallel, then tiny logit)
__global__ void k_w2(const float* __restrict__ W2) {
    __shared__ float sv[FF];
    int r = blockIdx.x, f = threadIdx.x;
    sv[f] = g_s[r * FF + f];
    __syncthreads();
    float acc = 0.f;
#pragma unroll 8
    for (int k = 0; k < FF; k++)
        acc += sv[k] * W2[((size_t)r * FF + k) * FF + f];
    atomicAdd(&g_g[f], acc);
}

__global__ void k_logit(const float* __restrict__ b2, const float* __restrict__ Wc,
                        const float* __restrict__ bc, float* __restrict__ out) {
    __shared__ float g[FF];
    int f = threadIdx.x;
    float gb = 0.f;
#pragma unroll
    for (int r = 0; r < RR; r++) gb += b2[r * FF + f];
    g[f] = g_g[f] * (1.f / NN) + gb;
    __syncthreads();
    if (f < 2) {
        float o = bc[f];
        for (int k = 0; k < FF; k++) o += g[k] * Wc[k * 2 + f];
        out[f] = o;
    }
}

// ---------------- launch ----------------
extern "C" void kernel_launch(void* const* d_in, const int* in_sizes, int n_in,
                              void* d_out, int out_size) {
    const float* x    = (const float*)d_in[0];
    const int*   esrc = (const int*)  d_in[1];
    const int*   edst = (const int*)  d_in[2];
    const float* W1   = (const float*)d_in[3];
    const float* b1   = (const float*)d_in[4];
    const float* W2   = (const float*)d_in[5];
    const float* b2   = (const float*)d_in[6];
    const float* Wc   = (const float*)d_in[7];
    const float* bc   = (const float*)d_in[8];
    float* out = (float*)d_out;

    void *p_do, *p_di, *p_cur, *p_c, *p_s, *p_g;
    cudaGetSymbolAddress(&p_do,  g_deg_out);
    cudaGetSymbolAddress(&p_di,  g_deg_in);
    cudaGetSymbolAddress(&p_cur, g_cursor2);
    cudaGetSymbolAddress(&p_c,   g_c);
    cudaGetSymbolAddress(&p_s,   g_s);
    cudaGetSymbolAddress(&p_g,   g_g);

    // ---- fork: side stream runs the dense (tensor-pipe) chain ----
    cudaEventRecord(g_evF, 0);
    cudaStreamWaitEvent(g_s2, g_evF, 0);

    k_prepX<<<(NN * FF / 4 + 255) / 256, 256, 0, g_s2>>>(x);
    k_prepB<<<(RR * FF * FF + 255) / 256, 256, 0, g_s2>>>(W1);
    k_bsum1<<<1, FF, 0, g_s2>>>(b1);
    k_gemmZ<<<dim3(782, 6), 256, GEMM_SMEM, g_s2>>>();
    cudaEventRecord(g_evJ, g_s2);

    // ---- main stream: graph prep (L2-atomic-bound) ----
    cudaMemsetAsync(p_do,  0, (size_t)RN * 4, 0);
    cudaMemsetAsync(p_di,  0, (size_t)RN * 4, 0);
    cudaMemsetAsync(p_cur, 0, (size_t)NN * 4, 0);
    cudaMemsetAsync(p_c,   0, (size_t)RN * 4, 0);
    cudaMemsetAsync(p_s,   0, (size_t)RR * FF * 4, 0);
    cudaMemsetAsync(p_g,   0, (size_t)FF * 4, 0);

    k_deg  <<<(RE + 255) / 256, 256>>>(esrc, edst);
    k_norm <<<(RN + 255) / 256, 256>>>();
    k_deg2 <<<(NN + 255) / 256, 256>>>();
    k_dscan1<<<NB2, 1024>>>();
    k_dscan2<<<1, 128>>>();
    k_dscan3<<<NB2, 1024>>>();
    k_fill2<<<(RE + 255) / 256, 256>>>(esrc, edst);

    // ---- join: aggregation needs both Z (s2) and the CSR (main) ----
    cudaStreamWaitEvent(0, g_evJ, 0);
    k_agg2 <<<(NN * 32 + 255) / 256, 256>>>();
    k_reduce<<<(NN + 127) / 128, 128>>>();
    k_w2   <<<RR, FF>>>(W2);
    k_logit<<<1, FF>>>(b2, Wc, bc, out);
}